// round 1
// baseline (speedup 1.0000x reference)
#include <cuda_runtime.h>
#include <stdint.h>

// Problem constants (shapes fixed by the reference)
#define D_IN   64
#define D_OUT  128
#define MAX_NODES 100000

// Scratch: rst[n][d] = feat[n][d] + sum_{e: dst[e]==n} feat[src[e]][d]
__device__ float g_rst[MAX_NODES * D_IN];

// ---------------------------------------------------------------------------
// Kernel 1: init rst = feat (vectorized copy). Runs every launch (graph-safe).
// ---------------------------------------------------------------------------
__global__ void init_rst_kernel(const float4* __restrict__ feat4, int n4) {
    int i = blockIdx.x * blockDim.x + threadIdx.x;
    if (i < n4) {
        reinterpret_cast<float4*>(g_rst)[i] = feat4[i];
    }
}

// ---------------------------------------------------------------------------
// Kernel 2: edge scatter. Work item = (edge, 16B chunk). 16 chunks per edge
// cover D_IN=64 floats. Gather feat[src] (L2-resident), vector-atomic-add
// into g_rst[dst] via red.global.add.v4.f32 (sm_90+).
// ---------------------------------------------------------------------------
__global__ void scatter_edges_kernel(const float4* __restrict__ feat4,
                                     const int* __restrict__ src,
                                     const int* __restrict__ dst,
                                     int nwork) {
    int i = blockIdx.x * blockDim.x + threadIdx.x;
    if (i >= nwork) return;
    int e = i >> 4;        // edge index
    int c = i & 15;        // float4 chunk within the 64-float row
    int s = __ldg(&src[e]);
    int d = __ldg(&dst[e]);
    float4 v = feat4[(size_t)s * 16 + c];
    float4* p = reinterpret_cast<float4*>(g_rst) + (size_t)d * 16 + c;
    asm volatile("red.global.add.v4.f32 [%0], {%1, %2, %3, %4};"
                 :: "l"(p), "f"(v.x), "f"(v.y), "f"(v.z), "f"(v.w)
                 : "memory");
}

// ---------------------------------------------------------------------------
// Kernel 3: out[n][o] = b[o] + sum_d rst[n][d] * W[o][d]
// Block = 128 threads (one per output column), 8 nodes per block.
// W row for column o lives in registers (64 floats); rst rows staged in smem.
// ---------------------------------------------------------------------------
#define NODES_PER_BLOCK 8

__global__ __launch_bounds__(D_OUT, 4)
void gemm_out_kernel(const float* __restrict__ W,
                     const float* __restrict__ b,
                     float* __restrict__ out,
                     int n) {
    __shared__ float s_rst[NODES_PER_BLOCK][D_IN];

    int t = threadIdx.x;          // output column 0..127
    int node0 = blockIdx.x * NODES_PER_BLOCK;

    // Stage 8 rst rows: 8*64 floats = 128 float4 -> one float4 per thread.
    {
        int idx = t;                       // 0..127
        int node = node0 + (idx >> 4);     // idx/16
        float4 v = make_float4(0.f, 0.f, 0.f, 0.f);
        if (node < n) {
            v = reinterpret_cast<const float4*>(g_rst)[(size_t)node * 16 + (idx & 15)];
        }
        reinterpret_cast<float4*>(&s_rst[0][0])[idx] = v;
    }
    __syncthreads();

    // Load this column's W row into registers (16 float4 = 64 floats).
    float w[D_IN];
    const float4* Wrow4 = reinterpret_cast<const float4*>(W + (size_t)t * D_IN);
    #pragma unroll
    for (int k = 0; k < D_IN / 4; k++) {
        float4 wv = __ldg(&Wrow4[k]);
        w[4 * k + 0] = wv.x;
        w[4 * k + 1] = wv.y;
        w[4 * k + 2] = wv.z;
        w[4 * k + 3] = wv.w;
    }
    float bias = __ldg(&b[t]);

    #pragma unroll
    for (int i = 0; i < NODES_PER_BLOCK; i++) {
        int node = node0 + i;
        if (node >= n) break;
        float acc = bias;
        #pragma unroll
        for (int d = 0; d < D_IN; d++) {
            acc += s_rst[i][d] * w[d];   // smem broadcast (all lanes same addr)
        }
        out[(size_t)node * D_OUT + t] = acc;
    }
}

// ---------------------------------------------------------------------------
// Launch contract
// Inputs (metadata order): feat [N*64] f32, radius [E] f32 (unused -> weight
// is ones_like), src [E] i32, dst [E] i32, W [128*64] f32, b [128] f32.
// Output: [N*128] f32.
// ---------------------------------------------------------------------------
extern "C" void kernel_launch(void* const* d_in, const int* in_sizes, int n_in,
                              void* d_out, int out_size) {
    const float* feat = (const float*)d_in[0];
    const int*   src  = (const int*)d_in[2];
    const int*   dst  = (const int*)d_in[3];
    const float* W    = (const float*)d_in[4];
    const float* b    = (const float*)d_in[5];
    float* out = (float*)d_out;

    int n = in_sizes[0] / D_IN;   // 100000
    int e = in_sizes[2];          // 1600000

    // 1) rst = feat
    int n4 = n * (D_IN / 4);      // number of float4 elements
    {
        int threads = 256;
        int blocks = (n4 + threads - 1) / threads;
        init_rst_kernel<<<blocks, threads>>>(
            reinterpret_cast<const float4*>(feat), n4);
    }

    // 2) rst[dst] += feat[src]
    {
        int nwork = e * 16;       // 16 float4 chunks per edge
        int threads = 256;
        int blocks = (nwork + threads - 1) / threads;
        scatter_edges_kernel<<<blocks, threads>>>(
            reinterpret_cast<const float4*>(feat), src, dst, nwork);
    }

    // 3) out = rst @ W^T + b
    {
        int blocks = (n + NODES_PER_BLOCK - 1) / NODES_PER_BLOCK;
        gemm_out_kernel<<<blocks, D_OUT>>>(W, b, out, n);
    }
}

// round 2
// speedup vs baseline: 1.0983x; 1.0983x over previous
#include <cuda_runtime.h>
#include <stdint.h>

#define D_IN   64
#define D_OUT  128
#define MAX_NODES 100000
#define MAX_EDGES 1600000

#define SCAN_CHUNK 4096           // elements per scan block (1024 thr * 4)
#define SCAN_BLOCKS ((MAX_NODES + 1 + SCAN_CHUNK - 1) / SCAN_CHUNK)   // 25

// Scratch (device globals; no allocs allowed)
__device__ int   g_cnt[MAX_NODES + 1];     // per-dst counts (+1 pad for total)
__device__ int   g_off[MAX_NODES + 1];     // exclusive offsets (CSR row ptr)
__device__ int   g_cur[MAX_NODES];         // fill cursors
__device__ int   g_esrc[MAX_EDGES];        // src ids sorted by dst bucket
__device__ int   g_bsum[SCAN_BLOCKS];      // scan block sums
__device__ float g_rst[MAX_NODES * D_IN];  // feat + mailbox sum

// ---------------------------------------------------------------------------
// 1) zero counts
// ---------------------------------------------------------------------------
__global__ void zero_cnt_kernel(int nelem) {
    int i = blockIdx.x * blockDim.x + threadIdx.x;
    if (i < nelem) g_cnt[i] = 0;
}

// ---------------------------------------------------------------------------
// 2) histogram of dst
// ---------------------------------------------------------------------------
__global__ void hist_kernel(const int* __restrict__ dst, int e) {
    int i = blockIdx.x * blockDim.x + threadIdx.x;
    if (i < e) atomicAdd(&g_cnt[dst[i]], 1);
}

// ---------------------------------------------------------------------------
// 3a) per-block exclusive scan (1024 threads x 4 elems)
// ---------------------------------------------------------------------------
__global__ __launch_bounds__(1024)
void scan1_kernel(int nelem) {
    __shared__ int s[1024];
    int t = threadIdx.x;
    int base = blockIdx.x * SCAN_CHUNK + t * 4;

    int v0 = (base + 0 < nelem) ? g_cnt[base + 0] : 0;
    int v1 = (base + 1 < nelem) ? g_cnt[base + 1] : 0;
    int v2 = (base + 2 < nelem) ? g_cnt[base + 2] : 0;
    int v3 = (base + 3 < nelem) ? g_cnt[base + 3] : 0;
    int tsum = v0 + v1 + v2 + v3;

    s[t] = tsum;
    __syncthreads();
    // Hillis-Steele inclusive scan over 1024 thread sums
    #pragma unroll
    for (int off = 1; off < 1024; off <<= 1) {
        int x = (t >= off) ? s[t - off] : 0;
        __syncthreads();
        if (t >= off) s[t] += x;
        __syncthreads();
    }
    int excl = s[t] - tsum;
    if (t == 1023) g_bsum[blockIdx.x] = s[1023];

    int run = excl;
    if (base + 0 < nelem) { g_off[base + 0] = run; } run += v0;
    if (base + 1 < nelem) { g_off[base + 1] = run; } run += v1;
    if (base + 2 < nelem) { g_off[base + 2] = run; } run += v2;
    if (base + 3 < nelem) { g_off[base + 3] = run; }
}

// 3b) exclusive scan of the 25 block sums (single thread, trivial size)
__global__ void scan2_kernel(int nblocks) {
    if (threadIdx.x == 0 && blockIdx.x == 0) {
        int run = 0;
        for (int i = 0; i < nblocks; i++) {
            int tmp = g_bsum[i];
            g_bsum[i] = run;
            run += tmp;
        }
    }
}

// 3c) add block offsets; snapshot cursors
__global__ void scan3_kernel(int nelem, int n) {
    int i = blockIdx.x * blockDim.x + threadIdx.x;
    if (i < nelem) {
        int o = g_off[i] + g_bsum[i / SCAN_CHUNK];
        g_off[i] = o;
        if (i < n) g_cur[i] = o;
    }
}

// ---------------------------------------------------------------------------
// 4) fill sorted src list
// ---------------------------------------------------------------------------
__global__ void fill_kernel(const int* __restrict__ src,
                            const int* __restrict__ dst, int e) {
    int i = blockIdx.x * blockDim.x + threadIdx.x;
    if (i < e) {
        int d = dst[i];
        int p = atomicAdd(&g_cur[d], 1);
        g_esrc[p] = src[i];
    }
}

// ---------------------------------------------------------------------------
// 5) segment reduce: warp per node, lane owns float2 of the 64-dim row.
//    rst[n] = feat[n] + sum_{e in bucket(n)} feat[src[e]]
// ---------------------------------------------------------------------------
__global__ __launch_bounds__(256)
void accumulate_kernel(const float2* __restrict__ feat2, int n) {
    int warp = (blockIdx.x * blockDim.x + threadIdx.x) >> 5;
    int lane = threadIdx.x & 31;
    if (warp >= n) return;

    int node = warp;
    float2 acc = feat2[(size_t)node * 32 + lane];

    int j   = g_off[node];
    int end = g_off[node + 1];

    // 4-way unrolled for memory-level parallelism
    for (; j + 4 <= end; j += 4) {
        int s0 = g_esrc[j + 0];
        int s1 = g_esrc[j + 1];
        int s2 = g_esrc[j + 2];
        int s3 = g_esrc[j + 3];
        float2 v0 = feat2[(size_t)s0 * 32 + lane];
        float2 v1 = feat2[(size_t)s1 * 32 + lane];
        float2 v2 = feat2[(size_t)s2 * 32 + lane];
        float2 v3 = feat2[(size_t)s3 * 32 + lane];
        acc.x += (v0.x + v1.x) + (v2.x + v3.x);
        acc.y += (v0.y + v1.y) + (v2.y + v3.y);
    }
    for (; j < end; j++) {
        int s = g_esrc[j];
        float2 v = feat2[(size_t)s * 32 + lane];
        acc.x += v.x;
        acc.y += v.y;
    }

    reinterpret_cast<float2*>(g_rst)[(size_t)node * 32 + lane] = acc;
}

// ---------------------------------------------------------------------------
// 6) out[n][o] = b[o] + sum_d rst[n][d] * W[o][d]
// ---------------------------------------------------------------------------
#define NODES_PER_BLOCK 8

__global__ __launch_bounds__(D_OUT, 4)
void gemm_out_kernel(const float* __restrict__ W,
                     const float* __restrict__ b,
                     float* __restrict__ out,
                     int n) {
    __shared__ float s_rst[NODES_PER_BLOCK][D_IN];

    int t = threadIdx.x;          // output column 0..127
    int node0 = blockIdx.x * NODES_PER_BLOCK;

    {   // stage 8 rst rows: 128 float4 -> one per thread
        int idx = t;
        int node = node0 + (idx >> 4);
        float4 v = make_float4(0.f, 0.f, 0.f, 0.f);
        if (node < n) {
            v = reinterpret_cast<const float4*>(g_rst)[(size_t)node * 16 + (idx & 15)];
        }
        reinterpret_cast<float4*>(&s_rst[0][0])[idx] = v;
    }
    __syncthreads();

    float w[D_IN];
    const float4* Wrow4 = reinterpret_cast<const float4*>(W + (size_t)t * D_IN);
    #pragma unroll
    for (int k = 0; k < D_IN / 4; k++) {
        float4 wv = __ldg(&Wrow4[k]);
        w[4 * k + 0] = wv.x;
        w[4 * k + 1] = wv.y;
        w[4 * k + 2] = wv.z;
        w[4 * k + 3] = wv.w;
    }
    float bias = __ldg(&b[t]);

    #pragma unroll
    for (int i = 0; i < NODES_PER_BLOCK; i++) {
        int node = node0 + i;
        if (node >= n) break;
        float acc = bias;
        #pragma unroll
        for (int d = 0; d < D_IN; d++) {
            acc += s_rst[i][d] * w[d];
        }
        out[(size_t)node * D_OUT + t] = acc;
    }
}

// ---------------------------------------------------------------------------
// Inputs: feat [N*64] f32, radius [E] f32 (dead: weight = ones_like),
//         src [E] i32, dst [E] i32, W [128*64] f32, b [128] f32.
// Output: [N*128] f32.
// ---------------------------------------------------------------------------
extern "C" void kernel_launch(void* const* d_in, const int* in_sizes, int n_in,
                              void* d_out, int out_size) {
    const float* feat = (const float*)d_in[0];
    const int*   src  = (const int*)d_in[2];
    const int*   dst  = (const int*)d_in[3];
    const float* W    = (const float*)d_in[4];
    const float* b    = (const float*)d_in[5];
    float* out = (float*)d_out;

    int n = in_sizes[0] / D_IN;   // 100000
    int e = in_sizes[2];          // 1600000
    int nelem = n + 1;

    // CSR build (counting sort by dst)
    zero_cnt_kernel<<<(nelem + 255) / 256, 256>>>(nelem);
    hist_kernel<<<(e + 255) / 256, 256>>>(dst, e);
    int nsb = (nelem + SCAN_CHUNK - 1) / SCAN_CHUNK;
    scan1_kernel<<<nsb, 1024>>>(nelem);
    scan2_kernel<<<1, 32>>>(nsb);
    scan3_kernel<<<(nelem + 255) / 256, 256>>>(nelem, n);
    fill_kernel<<<(e + 255) / 256, 256>>>(src, dst, e);

    // Segment reduce: warp per node (8 warps per 256-thread block)
    {
        int warps_per_block = 256 / 32;
        int blocks = (n + warps_per_block - 1) / warps_per_block;
        accumulate_kernel<<<blocks, 256>>>(
            reinterpret_cast<const float2*>(feat), n);
    }

    // out = rst @ W^T + b
    gemm_out_kernel<<<(n + NODES_PER_BLOCK - 1) / NODES_PER_BLOCK, D_OUT>>>(
        W, b, out, n);
}

// round 3
// speedup vs baseline: 1.3708x; 1.2481x over previous
#include <cuda_runtime.h>
#include <stdint.h>

#define D_IN   64
#define D_OUT  128
#define MAX_NODES 100000
#define MAX_EDGES 1600000

#define SCAN_CHUNK 4096           // elements per scan block (1024 thr * 4)
#define SCAN_BLOCKS ((MAX_NODES + 1 + SCAN_CHUNK - 1) / SCAN_CHUNK)   // 25

// Scratch (device globals; no allocs allowed)
__device__ int   g_cnt[MAX_NODES + 1];
__device__ int   g_off[MAX_NODES + 1];
__device__ int   g_cur[MAX_NODES];
__device__ int   g_esrc[MAX_EDGES];
__device__ int   g_bsum[SCAN_BLOCKS];
__device__ float g_rst[MAX_NODES * D_IN];

// ---------------------------------------------------------------------------
// 1) zero counts
// ---------------------------------------------------------------------------
__global__ void zero_cnt_kernel(int nelem) {
    int i = blockIdx.x * blockDim.x + threadIdx.x;
    if (i < nelem) g_cnt[i] = 0;
}

// ---------------------------------------------------------------------------
// 2) histogram of dst
// ---------------------------------------------------------------------------
__global__ void hist_kernel(const int* __restrict__ dst, int e) {
    int i = blockIdx.x * blockDim.x + threadIdx.x;
    if (i < e) atomicAdd(&g_cnt[dst[i]], 1);
}

// ---------------------------------------------------------------------------
// 3a) per-block exclusive scan (1024 threads x 4 elems)
// ---------------------------------------------------------------------------
__global__ __launch_bounds__(1024)
void scan1_kernel(int nelem) {
    __shared__ int s[1024];
    int t = threadIdx.x;
    int base = blockIdx.x * SCAN_CHUNK + t * 4;

    int v0 = (base + 0 < nelem) ? g_cnt[base + 0] : 0;
    int v1 = (base + 1 < nelem) ? g_cnt[base + 1] : 0;
    int v2 = (base + 2 < nelem) ? g_cnt[base + 2] : 0;
    int v3 = (base + 3 < nelem) ? g_cnt[base + 3] : 0;
    int tsum = v0 + v1 + v2 + v3;

    s[t] = tsum;
    __syncthreads();
    #pragma unroll
    for (int off = 1; off < 1024; off <<= 1) {
        int x = (t >= off) ? s[t - off] : 0;
        __syncthreads();
        if (t >= off) s[t] += x;
        __syncthreads();
    }
    int excl = s[t] - tsum;
    if (t == 1023) g_bsum[blockIdx.x] = s[1023];

    int run = excl;
    if (base + 0 < nelem) { g_off[base + 0] = run; } run += v0;
    if (base + 1 < nelem) { g_off[base + 1] = run; } run += v1;
    if (base + 2 < nelem) { g_off[base + 2] = run; } run += v2;
    if (base + 3 < nelem) { g_off[base + 3] = run; }
}

// 3b) exclusive scan of the block sums — single warp shfl scan (nblocks<=32)
__global__ void scan2_kernel(int nblocks) {
    int lane = threadIdx.x;
    int v = (lane < nblocks) ? g_bsum[lane] : 0;
    int orig = v;
    #pragma unroll
    for (int off = 1; off < 32; off <<= 1) {
        int x = __shfl_up_sync(0xFFFFFFFFu, v, off);
        if (lane >= off) v += x;
    }
    if (lane < nblocks) g_bsum[lane] = v - orig;   // exclusive
}

// 3c) add block offsets; snapshot cursors
__global__ void scan3_kernel(int nelem, int n) {
    int i = blockIdx.x * blockDim.x + threadIdx.x;
    if (i < nelem) {
        int o = g_off[i] + g_bsum[i / SCAN_CHUNK];
        g_off[i] = o;
        if (i < n) g_cur[i] = o;
    }
}

// ---------------------------------------------------------------------------
// 4) fill sorted src list
// ---------------------------------------------------------------------------
__global__ void fill_kernel(const int* __restrict__ src,
                            const int* __restrict__ dst, int e) {
    int i = blockIdx.x * blockDim.x + threadIdx.x;
    if (i < e) {
        int d = dst[i];
        int p = atomicAdd(&g_cur[d], 1);
        g_esrc[p] = src[i];
    }
}

// ---------------------------------------------------------------------------
// 5) segment reduce: warp per node, lane owns float2 of the 64-dim row.
//    8-deep unroll, two independent accumulator chains for MLP.
// ---------------------------------------------------------------------------
__global__ __launch_bounds__(256)
void accumulate_kernel(const float2* __restrict__ feat2, int n) {
    int warp = (blockIdx.x * blockDim.x + threadIdx.x) >> 5;
    int lane = threadIdx.x & 31;
    if (warp >= n) return;

    int node = warp;
    float2 acc0 = feat2[(size_t)node * 32 + lane];
    float2 acc1 = make_float2(0.f, 0.f);

    int j   = __ldg(&g_off[node]);
    int end = __ldg(&g_off[node + 1]);

    for (; j + 8 <= end; j += 8) {
        int s0 = __ldg(&g_esrc[j + 0]);
        int s1 = __ldg(&g_esrc[j + 1]);
        int s2 = __ldg(&g_esrc[j + 2]);
        int s3 = __ldg(&g_esrc[j + 3]);
        int s4 = __ldg(&g_esrc[j + 4]);
        int s5 = __ldg(&g_esrc[j + 5]);
        int s6 = __ldg(&g_esrc[j + 6]);
        int s7 = __ldg(&g_esrc[j + 7]);
        float2 v0 = feat2[(size_t)s0 * 32 + lane];
        float2 v1 = feat2[(size_t)s1 * 32 + lane];
        float2 v2 = feat2[(size_t)s2 * 32 + lane];
        float2 v3 = feat2[(size_t)s3 * 32 + lane];
        float2 v4 = feat2[(size_t)s4 * 32 + lane];
        float2 v5 = feat2[(size_t)s5 * 32 + lane];
        float2 v6 = feat2[(size_t)s6 * 32 + lane];
        float2 v7 = feat2[(size_t)s7 * 32 + lane];
        acc0.x += (v0.x + v1.x) + (v2.x + v3.x);
        acc0.y += (v0.y + v1.y) + (v2.y + v3.y);
        acc1.x += (v4.x + v5.x) + (v6.x + v7.x);
        acc1.y += (v4.y + v5.y) + (v6.y + v7.y);
    }
    for (; j + 2 <= end; j += 2) {
        int s0 = __ldg(&g_esrc[j + 0]);
        int s1 = __ldg(&g_esrc[j + 1]);
        float2 v0 = feat2[(size_t)s0 * 32 + lane];
        float2 v1 = feat2[(size_t)s1 * 32 + lane];
        acc0.x += v0.x; acc0.y += v0.y;
        acc1.x += v1.x; acc1.y += v1.y;
    }
    if (j < end) {
        int s = __ldg(&g_esrc[j]);
        float2 v = feat2[(size_t)s * 32 + lane];
        acc0.x += v.x; acc0.y += v.y;
    }

    float2 outv = make_float2(acc0.x + acc1.x, acc0.y + acc1.y);
    reinterpret_cast<float2*>(g_rst)[(size_t)node * 32 + lane] = outv;
}

// ---------------------------------------------------------------------------
// 6) out[n][o] = b[o] + sum_d rst[n][d] * W[o][d]
//    thread = output column, 16 nodes/block, float4 smem reads.
// ---------------------------------------------------------------------------
#define NODES_PER_BLOCK 16

__global__ __launch_bounds__(D_OUT, 4)
void gemm_out_kernel(const float* __restrict__ W,
                     const float* __restrict__ b,
                     float* __restrict__ out,
                     int n) {
    __shared__ float4 s_rst4[NODES_PER_BLOCK * (D_IN / 4)];   // 16 nodes * 16 float4

    int t = threadIdx.x;          // output column 0..127
    int node0 = blockIdx.x * NODES_PER_BLOCK;

    // Stage 16 rst rows: 256 float4 -> 2 per thread.
    #pragma unroll
    for (int r = 0; r < 2; r++) {
        int idx = t + r * D_OUT;           // 0..255
        int node = node0 + (idx >> 4);
        float4 v = make_float4(0.f, 0.f, 0.f, 0.f);
        if (node < n) {
            v = reinterpret_cast<const float4*>(g_rst)[(size_t)node * 16 + (idx & 15)];
        }
        s_rst4[idx] = v;
    }
    __syncthreads();

    // W row for this column in registers (16 float4 = 64 floats)
    float4 w[D_IN / 4];
    const float4* Wrow4 = reinterpret_cast<const float4*>(W + (size_t)t * D_IN);
    #pragma unroll
    for (int k = 0; k < D_IN / 4; k++) {
        w[k] = __ldg(&Wrow4[k]);
    }
    float bias = __ldg(&b[t]);

    #pragma unroll
    for (int i = 0; i < NODES_PER_BLOCK; i++) {
        int node = node0 + i;
        if (node >= n) break;
        float acc = bias;
        const float4* r4 = &s_rst4[i * (D_IN / 4)];
        #pragma unroll
        for (int k = 0; k < D_IN / 4; k++) {
            float4 v = r4[k];                 // LDS.128 broadcast
            acc += v.x * w[k].x + v.y * w[k].y + v.z * w[k].z + v.w * w[k].w;
        }
        out[(size_t)node * D_OUT + t] = acc;
    }
}

// ---------------------------------------------------------------------------
// Inputs: feat [N*64] f32, radius [E] f32 (dead: weight = ones_like),
//         src [E] i32, dst [E] i32, W [128*64] f32, b [128] f32.
// Output: [N*128] f32.
// ---------------------------------------------------------------------------
extern "C" void kernel_launch(void* const* d_in, const int* in_sizes, int n_in,
                              void* d_out, int out_size) {
    const float* feat = (const float*)d_in[0];
    const int*   src  = (const int*)d_in[2];
    const int*   dst  = (const int*)d_in[3];
    const float* W    = (const float*)d_in[4];
    const float* b    = (const float*)d_in[5];
    float* out = (float*)d_out;

    int n = in_sizes[0] / D_IN;   // 100000
    int e = in_sizes[2];          // 1600000
    int nelem = n + 1;

    // CSR build (counting sort by dst)
    zero_cnt_kernel<<<(nelem + 255) / 256, 256>>>(nelem);
    hist_kernel<<<(e + 255) / 256, 256>>>(dst, e);
    int nsb = (nelem + SCAN_CHUNK - 1) / SCAN_CHUNK;
    scan1_kernel<<<nsb, 1024>>>(nelem);
    scan2_kernel<<<1, 32>>>(nsb);
    scan3_kernel<<<(nelem + 255) / 256, 256>>>(nelem, n);
    fill_kernel<<<(e + 255) / 256, 256>>>(src, dst, e);

    // Segment reduce: warp per node
    {
        int warps_per_block = 256 / 32;
        int blocks = (n + warps_per_block - 1) / warps_per_block;
        accumulate_kernel<<<blocks, 256>>>(
            reinterpret_cast<const float2*>(feat), n);
    }

    // out = rst @ W^T + b
    gemm_out_kernel<<<(n + NODES_PER_BLOCK - 1) / NODES_PER_BLOCK, D_OUT>>>(
        W, b, out, n);
}